// round 8
// baseline (speedup 1.0000x reference)
#include <cuda_runtime.h>
#include <cuda_bf16.h>
#include <math.h>

#define NN   4096
#define FF   256
#define ELLW 256
#define TBITS 19
#define TSIZE (1 << TBITS)
#define TMASK (TSIZE - 1)
#define SPT  1024

// ---------------- scratch (device globals) ----------------
__device__ int   g_hkey[TSIZE];
__device__ float g_hval[TSIZE];
__device__ float g_deg[NN];
__device__ float g_dinv[NN];
__device__ int   g_cnt[NN];
// transposed ELL: entry k of row r lives at [k*NN + r] (coalesced across rows)
__device__ unsigned short g_colT[ELLW * NN];
__device__ float2 g_lrli[ELLW * NN];
__device__ float g_Z1r[NN * FF], g_Z1i[NN * FF];
__device__ float g_Z2r[NN * FF], g_Z2i[NN * FF];
__device__ float g_H1r[NN * FF], g_H1i[NN * FF];
__device__ float g_H2r[NN * FF], g_H2i[NN * FF];

__device__ __forceinline__ unsigned hash_key(int key) {
    return ((unsigned)key * 2654435761u) >> (32 - TBITS);
}

// ---------------- graph build (R2-proven path) ----------------
__global__ void zero_kernel() {
    int idx = blockIdx.x * blockDim.x + threadIdx.x;
    if (idx < TSIZE) { g_hkey[idx] = -1; g_hval[idx] = 0.f; }
    if (idx < NN)    { g_deg[idx] = 0.f; g_cnt[idx] = 0; }
}

__global__ void insert_kernel(const int* __restrict__ edges,
                              const float* __restrict__ w, int E) {
    int e = blockIdx.x * blockDim.x + threadIdx.x;
    if (e >= E) return;
    int r = edges[e];
    int c = edges[E + e];
    float we = w[e];
    atomicAdd(&g_deg[r], 0.5f * we);
    atomicAdd(&g_deg[c], 0.5f * we);
    int key = (r << 12) | c;
    unsigned h = hash_key(key) & TMASK;
    while (true) {
        int prev = atomicCAS(&g_hkey[h], -1, key);
        if (prev == -1 || prev == key) { atomicAdd(&g_hval[h], we); break; }
        h = (h + 1) & TMASK;
    }
}

__global__ void dinv_kernel() {
    int i = blockIdx.x * blockDim.x + threadIdx.x;
    if (i < NN) {
        float d = g_deg[i];
        if (d == 0.f) d = 1.f;
        g_dinv[i] = rsqrtf(d);
    }
}

__device__ __forceinline__ float hash_lookup(int key, bool* found) {
    unsigned h = hash_key(key) & TMASK;
    while (true) {
        int k = g_hkey[h];
        if (k == key) { *found = true; return g_hval[h]; }
        if (k == -1)  { *found = false; return 0.f; }
        h = (h + 1) & TMASK;
    }
}

__device__ __forceinline__ void ell_push(int r, int c, float lre, float lim) {
    int slot = atomicAdd(&g_cnt[r], 1);
    if (slot < ELLW) {
        g_colT[slot * NN + r] = (unsigned short)c;
        g_lrli[slot * NN + r] = make_float2(lre, lim);
    }
}

__global__ void emit_kernel(const float* __restrict__ qp) {
    int s = blockIdx.x * blockDim.x + threadIdx.x;
    if (s >= TSIZE) return;
    int key = g_hkey[s];
    if (key < 0) return;
    int i = key >> 12;
    int j = key & 4095;
    float a = g_hval[s];
    float q = __ldg(qp);
    if (i == j) {
        float di = g_dinv[i];
        ell_push(i, i, -di * di * a, 0.f);
        return;
    }
    bool found;
    float at = hash_lookup((j << 12) | i, &found);
    if (i > j && found) return;   // handled by the (j,i) slot
    float asym = 0.5f * (a + at);
    float an = g_dinv[i] * asym * g_dinv[j];
    float th = 6.283185307179586f * q * (a - at);
    float sn, cs;
    sincosf(th, &sn, &cs);
    // conj(L)[i][j] = -A_n * exp(-i*th)
    ell_push(i, j, -an * cs,  an * sn);
    ell_push(j, i, -an * cs, -an * sn);
}

// ---------------- feature-tiled complex SpMM with smem-staged X slice ----------------
// Block = 1024 threads = 1024 rows, 4-feature tile. Stages the 4-feature complex
// slice of ALL 4096 X rows in 128KB smem (dedups the per-nnz gather), then each
// thread walks its own (transposed, coalesced) ELL row gathering from smem.
__global__ void __launch_bounds__(SPT, 1)
spmm_tiled_kernel(const float* __restrict__ Xr, const float* __restrict__ Xi,
                  const float* __restrict__ Sr, const float* __restrict__ Si,
                  float* __restrict__ Yr, float* __restrict__ Yi) {
    extern __shared__ float sx[];          // [4096][8] : 4 xr + 4 xi per column
    int tid = threadIdx.x;
    int f0 = blockIdx.x * 4;
    int row = blockIdx.y * SPT + tid;

    #pragma unroll
    for (int it = 0; it < 4; it++) {
        int col = it * SPT + tid;
        float4 vr = *reinterpret_cast<const float4*>(&Xr[col * FF + f0]);
        float4 vi = *reinterpret_cast<const float4*>(&Xi[col * FF + f0]);
        *reinterpret_cast<float4*>(&sx[col * 8])     = vr;
        *reinterpret_cast<float4*>(&sx[col * 8 + 4]) = vi;
    }
    __syncthreads();

    int cnt = g_cnt[row];
    if (cnt > ELLW) cnt = ELLW;
    float yr0 = 0.f, yr1 = 0.f, yr2 = 0.f, yr3 = 0.f;
    float yi0 = 0.f, yi1 = 0.f, yi2 = 0.f, yi3 = 0.f;
    for (int k = 0; k < cnt; k++) {
        int c = (int)g_colT[k * NN + row];
        float2 l = g_lrli[k * NN + row];
        float4 xr = *reinterpret_cast<const float4*>(&sx[c * 8]);
        float4 xi = *reinterpret_cast<const float4*>(&sx[c * 8 + 4]);
        yr0 = fmaf(l.x, xr.x, yr0); yr0 = fmaf(-l.y, xi.x, yr0);
        yr1 = fmaf(l.x, xr.y, yr1); yr1 = fmaf(-l.y, xi.y, yr1);
        yr2 = fmaf(l.x, xr.z, yr2); yr2 = fmaf(-l.y, xi.z, yr2);
        yr3 = fmaf(l.x, xr.w, yr3); yr3 = fmaf(-l.y, xi.w, yr3);
        yi0 = fmaf(l.x, xi.x, yi0); yi0 = fmaf(l.y, xr.x, yi0);
        yi1 = fmaf(l.x, xi.y, yi1); yi1 = fmaf(l.y, xr.y, yi1);
        yi2 = fmaf(l.x, xi.z, yi2); yi2 = fmaf(l.y, xr.z, yi2);
        yi3 = fmaf(l.x, xi.w, yi3); yi3 = fmaf(l.y, xr.w, yi3);
    }

    int o = row * FF + f0;
    float4 outr, outi;
    if (Sr) {
        float4 sr = *reinterpret_cast<const float4*>(&Sr[o]);
        float4 si = *reinterpret_cast<const float4*>(&Si[o]);
        outr = make_float4(2.f * yr0 - sr.x, 2.f * yr1 - sr.y, 2.f * yr2 - sr.z, 2.f * yr3 - sr.w);
        outi = make_float4(2.f * yi0 - si.x, 2.f * yi1 - si.y, 2.f * yi2 - si.z, 2.f * yi3 - si.w);
    } else {
        outr = make_float4(yr0, yr1, yr2, yr3);
        outi = make_float4(yi0, yi1, yi2, yi3);
    }
    *reinterpret_cast<float4*>(&Yr[o]) = outr;
    *reinterpret_cast<float4*>(&Yi[o]) = outi;
}

// ---------------- fused tensor-core GEMM (R7-proven, verbatim) ----------------
__device__ __forceinline__ unsigned pack_bf2(float x, float y) {
    __nv_bfloat162 t;
    t.x = __float2bfloat16_rn(x);
    t.y = __float2bfloat16_rn(y);
    return *reinterpret_cast<unsigned*>(&t);
}

#define MMA_BF16(d, a, b)                                                        \
    asm volatile("mma.sync.aligned.m16n8k16.row.col.f32.bf16.bf16.f32 "          \
                 "{%0,%1,%2,%3},{%4,%5,%6,%7},{%8,%9},{%0,%1,%2,%3};"            \
                 : "+f"(d[0]), "+f"(d[1]), "+f"(d[2]), "+f"(d[3])                 \
                 : "r"(a[0]), "r"(a[1]), "r"(a[2]), "r"(a[3]), "r"(b[0]), "r"(b[1]))

#define LDSM_X4(r, addr)                                                         \
    asm volatile("ldmatrix.sync.aligned.m8n8.x4.shared.b16 {%0,%1,%2,%3}, [%4];" \
                 : "=r"(r[0]), "=r"(r[1]), "=r"(r[2]), "=r"(r[3]) : "r"(addr) : "memory")

#define LDSM_X4_T(r, addr)                                                             \
    asm volatile("ldmatrix.sync.aligned.m8n8.x4.trans.shared.b16 {%0,%1,%2,%3}, [%4];" \
                 : "=r"(r[0]), "=r"(r[1]), "=r"(r[2]), "=r"(r[3]) : "r"(addr) : "memory")

#define AST 20   // A smem row stride in uints (40 bf16 = 80B, LDSM conflict-free)
#define WST 36   // W smem row stride in uints (72 bf16 = 144B, LDSM.T conflict-free)

__global__ void __launch_bounds__(256, 2)
gemm_fused_kernel(const float* __restrict__ A0r, const float* __restrict__ A1r,
                  const float* __restrict__ A2r, const float* __restrict__ A0i,
                  const float* __restrict__ A1i, const float* __restrict__ A2i,
                  const float* __restrict__ W, const float* __restrict__ bias,
                  float* __restrict__ Hr, float* __restrict__ Hi) {
    __shared__ unsigned ash[128 * AST], asl[128 * AST];
    __shared__ unsigned wsh[32 * WST],  wsl[32 * WST];

    int tid = threadIdx.x;
    int lane = tid & 31;
    int warp = tid >> 5;
    int wm = warp >> 2;          // 0..1
    int wn = warp & 3;           // 0..3
    int m0 = blockIdx.y * 128;   // 0..8064
    int n0 = blockIdx.x * 64;
    bool isImag = (m0 >= 4096);
    int mrow0 = m0 & 4095;

    float acc[4][2][4];
    #pragma unroll
    for (int mt = 0; mt < 4; mt++)
        #pragma unroll
        for (int nt = 0; nt < 2; nt++)
            #pragma unroll
            for (int r = 0; r < 4; r++) acc[mt][nt][r] = 0.f;

    unsigned a_hi_base = (unsigned)__cvta_generic_to_shared(ash);
    unsigned a_lo_base = (unsigned)__cvta_generic_to_shared(asl);
    unsigned w_hi_base = (unsigned)__cvta_generic_to_shared(wsh);
    unsigned w_lo_base = (unsigned)__cvta_generic_to_shared(wsl);

    unsigned a_off = ((wm * 64 + (lane & 15)) * (AST * 2) + (lane >> 4) * 8) * 2;
    unsigned w_off = (((((lane >> 3) & 1) * 8 + (lane & 7)) * (WST * 2)) + wn * 16 + (lane >> 4) * 8) * 2;

    for (int ks = 0; ks < 24; ks++) {
        int k0 = ks * 32;
        int plane = k0 >> 8;
        int kc = k0 & 255;
        const float* Ap = isImag ? (plane == 0 ? A0i : (plane == 1 ? A1i : A2i))
                                 : (plane == 0 ? A0r : (plane == 1 ? A1r : A2r));
        // load A tile 128x32
        #pragma unroll
        for (int t = 0; t < 4; t++) {
            int idx = tid + t * 256;
            int r = idx >> 3;
            int c4 = (idx & 7) * 4;
            float4 v = *reinterpret_cast<const float4*>(&Ap[(mrow0 + r) * 256 + kc + c4]);
            float hx = __bfloat162float(__float2bfloat16_rn(v.x));
            float hy = __bfloat162float(__float2bfloat16_rn(v.y));
            float hz = __bfloat162float(__float2bfloat16_rn(v.z));
            float hw = __bfloat162float(__float2bfloat16_rn(v.w));
            int o = r * AST + (c4 >> 1);
            ash[o]     = pack_bf2(v.x, v.y);
            ash[o + 1] = pack_bf2(v.z, v.w);
            asl[o]     = pack_bf2(v.x - hx, v.y - hy);
            asl[o + 1] = pack_bf2(v.z - hz, v.w - hw);
        }
        // load W tile 32x64 (k-major): 2 iters x 256 thr x float4 = 2048 elems
        #pragma unroll
        for (int t = 0; t < 2; t++) {
            int idx = tid + t * 256;
            int kk = idx >> 4;          // 0..31
            int n4 = (idx & 15) * 4;    // 0..60
            float4 v = *reinterpret_cast<const float4*>(&W[plane * 65536 + (kc + kk) * 256 + n0 + n4]);
            float hx = __bfloat162float(__float2bfloat16_rn(v.x));
            float hy = __bfloat162float(__float2bfloat16_rn(v.y));
            float hz = __bfloat162float(__float2bfloat16_rn(v.z));
            float hw = __bfloat162float(__float2bfloat16_rn(v.w));
            int o = kk * WST + (n4 >> 1);
            wsh[o]     = pack_bf2(v.x, v.y);
            wsh[o + 1] = pack_bf2(v.z, v.w);
            wsl[o]     = pack_bf2(v.x - hx, v.y - hy);
            wsl[o + 1] = pack_bf2(v.z - hz, v.w - hw);
        }
        __syncthreads();

        #pragma unroll
        for (int h = 0; h < 32; h += 16) {
            unsigned ah[4][4], al[4][4];
            #pragma unroll
            for (int mt = 0; mt < 4; mt++) {
                unsigned off = a_off + (mt * 16 * AST * 2 + h) * 2;
                LDSM_X4(ah[mt], a_hi_base + off);
                LDSM_X4(al[mt], a_lo_base + off);
            }
            unsigned bh4[4], bl4[4];
            {
                unsigned off = w_off + (h * WST * 2) * 2;
                LDSM_X4_T(bh4, w_hi_base + off);
                LDSM_X4_T(bl4, w_lo_base + off);
            }
            #pragma unroll
            for (int mt = 0; mt < 4; mt++) {
                #pragma unroll
                for (int nt = 0; nt < 2; nt++) {
                    unsigned bh[2] = {bh4[nt * 2], bh4[nt * 2 + 1]};
                    unsigned bl[2] = {bl4[nt * 2], bl4[nt * 2 + 1]};
                    MMA_BF16(acc[mt][nt], ah[mt], bh);
                    MMA_BF16(acc[mt][nt], ah[mt], bl);
                    MMA_BF16(acc[mt][nt], al[mt], bh);
                }
            }
        }
        __syncthreads();
    }

    // epilogue
    int g = lane >> 2, tig = lane & 3;
    #pragma unroll
    for (int mt = 0; mt < 4; mt++) {
        #pragma unroll
        for (int nt = 0; nt < 2; nt++) {
            int n = n0 + wn * 16 + nt * 8 + tig * 2;
            float b0 = bias[n], b1v = bias[n + 1];
            int ml0 = mrow0 + wm * 64 + mt * 16 + g;
            float* c0 = acc[mt][nt];
            if (!isImag) {
                float2 o0 = make_float2(c0[0] + b0, c0[1] + b1v);
                float2 o1 = make_float2(c0[2] + b0, c0[3] + b1v);
                *reinterpret_cast<float2*>(&Hi[ml0 * 256 + n])       = o0;
                *reinterpret_cast<float2*>(&Hi[(ml0 + 8) * 256 + n]) = o1;
            } else {
                float2 o0 = make_float2(-c0[0] + b0, -c0[1] + b1v);
                float2 o1 = make_float2(-c0[2] + b0, -c0[3] + b1v);
                *reinterpret_cast<float2*>(&Hr[ml0 * 256 + n])       = o0;
                *reinterpret_cast<float2*>(&Hr[(ml0 + 8) * 256 + n]) = o1;
            }
        }
    }
}

// ---------------- classifier + log_softmax (R7-proven, verbatim) ----------------
__global__ void classifier_kernel(const float* __restrict__ Hr, const float* __restrict__ Hi,
                                  const float* __restrict__ Wc, const float* __restrict__ bc,
                                  float* __restrict__ out) {
    int row = blockIdx.x;
    int t = threadIdx.x;   // 128
    __shared__ float x[512];
    __shared__ float lg[40];
    for (int i = t; i < 256; i += 128) {
        x[i]       = Hr[row * 256 + i];
        x[i + 256] = Hi[row * 256 + i];
    }
    __syncthreads();
    int warp = t >> 5, lane = t & 31;
    for (int c = warp; c < 40; c += 4) {
        float s = 0.f;
        #pragma unroll
        for (int k = lane; k < 512; k += 32) s = fmaf(x[k], Wc[c * 512 + k], s);
        #pragma unroll
        for (int o = 16; o > 0; o >>= 1) s += __shfl_xor_sync(0xffffffffu, s, o);
        if (lane == 0) lg[c] = s + bc[c];
    }
    __syncthreads();
    if (warp == 0) {
        float a  = (lane < 40)      ? lg[lane]      : -3.4e38f;
        float b2 = (lane + 32 < 40) ? lg[lane + 32] : -3.4e38f;
        float m = fmaxf(a, b2);
        #pragma unroll
        for (int o = 16; o > 0; o >>= 1) m = fmaxf(m, __shfl_xor_sync(0xffffffffu, m, o));
        float s = ((lane < 40) ? expf(a - m) : 0.f) + ((lane + 32 < 40) ? expf(b2 - m) : 0.f);
        #pragma unroll
        for (int o = 16; o > 0; o >>= 1) s += __shfl_xor_sync(0xffffffffu, s, o);
        float lse = m + logf(s);
        if (lane < 40)      out[row * 40 + lane]      = a - lse;
        if (lane + 32 < 40) out[row * 40 + lane + 32] = b2 - lse;
    }
}

// ---------------- launch ----------------
#define SPMM_SMEM (4096 * 8 * 4)   // 128KB X slice

extern "C" void kernel_launch(void* const* d_in, const int* in_sizes, int n_in,
                              void* d_out, int out_size) {
    const float* real = (const float*)d_in[0];
    const float* imag = (const float*)d_in[1];
    const int*   edges = (const int*)d_in[2];
    const float* qp = (const float*)d_in[3];
    const float* ew = (const float*)d_in[4];
    const float* W1 = (const float*)d_in[5];
    const float* b1 = (const float*)d_in[6];
    const float* W2 = (const float*)d_in[7];
    const float* b2 = (const float*)d_in[8];
    const float* Wc = (const float*)d_in[9];
    const float* bc = (const float*)d_in[10];
    float* out = (float*)d_out;
    int E = in_sizes[4];

    cudaFuncSetAttribute(spmm_tiled_kernel, cudaFuncAttributeMaxDynamicSharedMemorySize, SPMM_SMEM);

    float *Z1r, *Z1i, *Z2r, *Z2i, *H1r, *H1i, *H2r, *H2i;
    cudaGetSymbolAddress((void**)&Z1r, g_Z1r);
    cudaGetSymbolAddress((void**)&Z1i, g_Z1i);
    cudaGetSymbolAddress((void**)&Z2r, g_Z2r);
    cudaGetSymbolAddress((void**)&Z2i, g_Z2i);
    cudaGetSymbolAddress((void**)&H1r, g_H1r);
    cudaGetSymbolAddress((void**)&H1i, g_H1i);
    cudaGetSymbolAddress((void**)&H2r, g_H2r);
    cudaGetSymbolAddress((void**)&H2i, g_H2i);

    // graph build
    zero_kernel<<<TSIZE / 256, 256>>>();
    insert_kernel<<<(E + 255) / 256, 256>>>(edges, ew, E);
    dinv_kernel<<<NN / 256, 256>>>();
    emit_kernel<<<TSIZE / 256, 256>>>(qp);

    dim3 spgrid(FF / 4, NN / SPT);   // (64, 4)

    // ---- layer 1 ----
    spmm_tiled_kernel<<<spgrid, SPT, SPMM_SMEM>>>(real, imag, nullptr, nullptr, Z1r, Z1i);
    spmm_tiled_kernel<<<spgrid, SPT, SPMM_SMEM>>>(Z1r, Z1i, real, imag, Z2r, Z2i);
    gemm_fused_kernel<<<dim3(4, 64), 256>>>(real, Z1r, Z2r, imag, Z1i, Z2i, W1, b1, H1r, H1i);

    // ---- layer 2 ----
    spmm_tiled_kernel<<<spgrid, SPT, SPMM_SMEM>>>(H1r, H1i, nullptr, nullptr, Z1r, Z1i);
    spmm_tiled_kernel<<<spgrid, SPT, SPMM_SMEM>>>(Z1r, Z1i, H1r, H1i, Z2r, Z2i);
    gemm_fused_kernel<<<dim3(4, 64), 256>>>(H1r, Z1r, Z2r, H1i, Z1i, Z2i, W2, b2, H2r, H2i);

    classifier_kernel<<<NN, 128>>>(H2r, H2i, Wc, bc, out);
}

// round 9
// speedup vs baseline: 1.5775x; 1.5775x over previous
#include <cuda_runtime.h>
#include <cuda_bf16.h>
#include <math.h>

#define NN   4096
#define FF   256
#define ELLW 256
#define TBITS 19
#define TSIZE (1 << TBITS)
#define TMASK (TSIZE - 1)

// ---------------- scratch (device globals) ----------------
__device__ int   g_hkey[TSIZE];
__device__ float g_hval[TSIZE];
__device__ float g_deg[NN];
__device__ float g_dinv[NN];
__device__ int   g_cnt[NN];
__device__ int   g_col[NN * ELLW];
__device__ float g_lre[NN * ELLW];
__device__ float g_lim[NN * ELLW];
__device__ float g_Z1r[NN * FF], g_Z1i[NN * FF];
__device__ float g_Z2r[NN * FF], g_Z2i[NN * FF];
__device__ float g_H1r[NN * FF], g_H1i[NN * FF];
__device__ float g_H2r[NN * FF], g_H2i[NN * FF];
__device__ float g_Cp[2 * NN * FF];          // partial C (8192 x 256 fp32)

__device__ __forceinline__ unsigned hash_key(int key) {
    return ((unsigned)key * 2654435761u) >> (32 - TBITS);
}

// ---------------- graph build (R2-proven) ----------------
__global__ void zero_kernel() {
    int idx = blockIdx.x * blockDim.x + threadIdx.x;
    if (idx < TSIZE) { g_hkey[idx] = -1; g_hval[idx] = 0.f; }
    if (idx < NN)    { g_deg[idx] = 0.f; g_cnt[idx] = 0; }
}

__global__ void insert_kernel(const int* __restrict__ edges,
                              const float* __restrict__ w, int E) {
    int e = blockIdx.x * blockDim.x + threadIdx.x;
    if (e >= E) return;
    int r = edges[e];
    int c = edges[E + e];
    float we = w[e];
    atomicAdd(&g_deg[r], 0.5f * we);
    atomicAdd(&g_deg[c], 0.5f * we);
    int key = (r << 12) | c;
    unsigned h = hash_key(key) & TMASK;
    while (true) {
        int prev = atomicCAS(&g_hkey[h], -1, key);
        if (prev == -1 || prev == key) { atomicAdd(&g_hval[h], we); break; }
        h = (h + 1) & TMASK;
    }
}

__global__ void dinv_kernel() {
    int i = blockIdx.x * blockDim.x + threadIdx.x;
    if (i < NN) {
        float d = g_deg[i];
        if (d == 0.f) d = 1.f;
        g_dinv[i] = rsqrtf(d);
    }
}

__device__ __forceinline__ float hash_lookup(int key, bool* found) {
    unsigned h = hash_key(key) & TMASK;
    while (true) {
        int k = g_hkey[h];
        if (k == key) { *found = true; return g_hval[h]; }
        if (k == -1)  { *found = false; return 0.f; }
        h = (h + 1) & TMASK;
    }
}

__device__ __forceinline__ void ell_push(int r, int c, float lre, float lim) {
    int slot = atomicAdd(&g_cnt[r], 1);
    if (slot < ELLW) {
        g_col[r * ELLW + slot] = c;
        g_lre[r * ELLW + slot] = lre;
        g_lim[r * ELLW + slot] = lim;
    }
}

__global__ void emit_kernel(const float* __restrict__ qp) {
    int s = blockIdx.x * blockDim.x + threadIdx.x;
    if (s >= TSIZE) return;
    int key = g_hkey[s];
    if (key < 0) return;
    int i = key >> 12;
    int j = key & 4095;
    float a = g_hval[s];
    float q = __ldg(qp);
    if (i == j) {
        float di = g_dinv[i];
        ell_push(i, i, -di * di * a, 0.f);
        return;
    }
    bool found;
    float at = hash_lookup((j << 12) | i, &found);
    if (i > j && found) return;   // handled by the (j,i) slot
    float asym = 0.5f * (a + at);
    float an = g_dinv[i] * asym * g_dinv[j];
    float th = 6.283185307179586f * q * (a - at);
    float sn, cs;
    sincosf(th, &sn, &cs);
    // conj(L)[i][j] = -A_n * exp(-i*th)
    ell_push(i, j, -an * cs,  an * sn);
    ell_push(j, i, -an * cs, -an * sn);
}

// ---------------- spmm device body (R2-proven gather) ----------------
__device__ __forceinline__ void spmm_row_body(
        char* smem, int row, int t,
        const float* __restrict__ Xr, const float* __restrict__ Xi,
        const float* __restrict__ Sr, const float* __restrict__ Si,
        float* __restrict__ Yr, float* __restrict__ Yi) {
    int*   sc  = (int*)smem;
    float* slr = (float*)(smem + 1024);
    float* sli = (float*)(smem + 2048);
    int cnt = g_cnt[row];
    if (cnt > ELLW) cnt = ELLW;
    for (int k = t; k < cnt; k += 256) {
        sc [k] = g_col[row * ELLW + k];
        slr[k] = g_lre[row * ELLW + k];
        sli[k] = g_lim[row * ELLW + k];
    }
    __syncthreads();
    float ar = 0.f, ai = 0.f;
    #pragma unroll 4
    for (int k = 0; k < cnt; k++) {
        int   c  = sc[k];
        float lr = slr[k];
        float li = sli[k];
        float xr = __ldg(&Xr[c * FF + t]);
        float xi = __ldg(&Xi[c * FF + t]);
        ar = fmaf(lr, xr, ar);
        ar = fmaf(-li, xi, ar);
        ai = fmaf(lr, xi, ai);
        ai = fmaf(li, xr, ai);
    }
    int o = row * FF + t;
    if (Sr) {
        Yr[o] = 2.f * ar - Sr[o];
        Yi[o] = 2.f * ai - Si[o];
    } else {
        Yr[o] = ar;
        Yi[o] = ai;
    }
}

__global__ void spmm_kernel(const float* __restrict__ Xr, const float* __restrict__ Xi,
                            const float* __restrict__ Sr, const float* __restrict__ Si,
                            float* __restrict__ Yr, float* __restrict__ Yi) {
    __shared__ char smem[3072];
    spmm_row_body(smem, blockIdx.x, threadIdx.x, Xr, Xi, Sr, Si, Yr, Yi);
}

// ---------------- GEMM machinery (R2-proven fragments/loaders) ----------------
__device__ __forceinline__ unsigned pack_bf2(float x, float y) {
    __nv_bfloat162 t;
    t.x = __float2bfloat16_rn(x);
    t.y = __float2bfloat16_rn(y);
    return *reinterpret_cast<unsigned*>(&t);
}

#define MMA_BF16(d, a, b)                                                        \
    asm volatile("mma.sync.aligned.m16n8k16.row.col.f32.bf16.bf16.f32 "          \
                 "{%0,%1,%2,%3},{%4,%5,%6,%7},{%8,%9},{%0,%1,%2,%3};"            \
                 : "+f"(d[0]), "+f"(d[1]), "+f"(d[2]), "+f"(d[3])                 \
                 : "r"(a[0]), "r"(a[1]), "r"(a[2]), "r"(a[3]), "r"(b[0]), "r"(b[1]))

#define LDSM_X4(r, addr)                                                         \
    asm volatile("ldmatrix.sync.aligned.m8n8.x4.shared.b16 {%0,%1,%2,%3}, [%4];" \
                 : "=r"(r[0]), "=r"(r[1]), "=r"(r[2]), "=r"(r[3]) : "r"(addr) : "memory")

#define LDSM_X4_T(r, addr)                                                             \
    asm volatile("ldmatrix.sync.aligned.m8n8.x4.trans.shared.b16 {%0,%1,%2,%3}, [%4];" \
                 : "=r"(r[0]), "=r"(r[1]), "=r"(r[2]), "=r"(r[3]) : "r"(addr) : "memory")

#define AST 20   // A smem row stride in uints (80B, LDSM conflict-free)
#define WST 36   // W smem row stride in uints (144B, LDSM.T conflict-free)
#define GEMM_SMEM_BYTES ((2 * 128 * AST + 2 * 32 * WST) * 4)   // 29696

// One k-chunk (32 wide): load A/W tiles with inline hi/lo split, then mma.
// Ap: fp32 A plane [4096x256]; Wp: fp32 W plane base [256x256].
__device__ __forceinline__ void gemm_chunk(
        unsigned* ash, unsigned* asl, unsigned* wsh, unsigned* wsl,
        unsigned a_hi_base, unsigned a_lo_base, unsigned w_hi_base, unsigned w_lo_base,
        unsigned a_off, unsigned w_off,
        const float* __restrict__ Ap, const float* __restrict__ Wp,
        int mrow0, int n0, int kc, int tid, float acc[4][2][4]) {
    // load A tile 128x32
    #pragma unroll
    for (int t = 0; t < 4; t++) {
        int idx = tid + t * 256;
        int r = idx >> 3;
        int c4 = (idx & 7) * 4;
        float4 v = *reinterpret_cast<const float4*>(&Ap[(mrow0 + r) * 256 + kc + c4]);
        float hx = __bfloat162float(__float2bfloat16_rn(v.x));
        float hy = __bfloat162float(__float2bfloat16_rn(v.y));
        float hz = __bfloat162float(__float2bfloat16_rn(v.z));
        float hw = __bfloat162float(__float2bfloat16_rn(v.w));
        int o = r * AST + (c4 >> 1);
        ash[o]     = pack_bf2(v.x, v.y);
        ash[o + 1] = pack_bf2(v.z, v.w);
        asl[o]     = pack_bf2(v.x - hx, v.y - hy);
        asl[o + 1] = pack_bf2(v.z - hz, v.w - hw);
    }
    // load W tile 32x64: 2 iters x 256 thr x float4 = 2048 elems
    #pragma unroll
    for (int t = 0; t < 2; t++) {
        int idx = tid + t * 256;
        int kk = idx >> 4;          // 0..31
        int n4 = (idx & 15) * 4;    // 0..60
        float4 v = *reinterpret_cast<const float4*>(&Wp[(kc + kk) * 256 + n0 + n4]);
        float hx = __bfloat162float(__float2bfloat16_rn(v.x));
        float hy = __bfloat162float(__float2bfloat16_rn(v.y));
        float hz = __bfloat162float(__float2bfloat16_rn(v.z));
        float hw = __bfloat162float(__float2bfloat16_rn(v.w));
        int o = kk * WST + (n4 >> 1);
        wsh[o]     = pack_bf2(v.x, v.y);
        wsh[o + 1] = pack_bf2(v.z, v.w);
        wsl[o]     = pack_bf2(v.x - hx, v.y - hy);
        wsl[o + 1] = pack_bf2(v.z - hz, v.w - hw);
    }
    __syncthreads();

    #pragma unroll
    for (int h = 0; h < 32; h += 16) {
        unsigned ah[4][4], al[4][4];
        #pragma unroll
        for (int mt = 0; mt < 4; mt++) {
            unsigned off = a_off + (mt * 16 * AST * 2 + h) * 2;
            LDSM_X4(ah[mt], a_hi_base + off);
            LDSM_X4(al[mt], a_lo_base + off);
        }
        unsigned bh4[4], bl4[4];
        {
            unsigned off = w_off + (h * WST * 2) * 2;
            LDSM_X4_T(bh4, w_hi_base + off);
            LDSM_X4_T(bl4, w_lo_base + off);
        }
        #pragma unroll
        for (int mt = 0; mt < 4; mt++) {
            #pragma unroll
            for (int nt = 0; nt < 2; nt++) {
                unsigned bh[2] = {bh4[nt * 2], bh4[nt * 2 + 1]};
                unsigned bl[2] = {bl4[nt * 2], bl4[nt * 2 + 1]};
                MMA_BF16(acc[mt][nt], ah[mt], bh);
                MMA_BF16(acc[mt][nt], ah[mt], bl);
                MMA_BF16(acc[mt][nt], al[mt], bh);
            }
        }
    }
    __syncthreads();
}

// ---------------- combined kernel: gemm_A (planes 0,1 -> Cp) + spmm2 ----------------
// blocks [0,256): gemm partial; blocks [256, 256+4096): spmm rows.
__global__ void combined_kernel(
        const float* __restrict__ Z1r, const float* __restrict__ Z1i,   // spmm X; gemm plane 1
        const float* __restrict__ Z0r, const float* __restrict__ Z0i,   // spmm S; gemm plane 0
        float* __restrict__ Z2r, float* __restrict__ Z2i,               // spmm out
        const float* __restrict__ W, float* __restrict__ Cp) {
    __shared__ char smem_u[GEMM_SMEM_BYTES];
    int tid = threadIdx.x;

    if (blockIdx.x >= 256) {
        spmm_row_body(smem_u, blockIdx.x - 256, tid, Z1r, Z1i, Z0r, Z0i, Z2r, Z2i);
        return;
    }

    // --- gemm_A: K = 512 (planes 0,1), raw partial accumulation into Cp ---
    unsigned* ash = (unsigned*)smem_u;
    unsigned* asl = ash + 128 * AST;
    unsigned* wsh = asl + 128 * AST;
    unsigned* wsl = wsh + 32 * WST;

    int lane = tid & 31;
    int warp = tid >> 5;
    int wm = warp >> 2;
    int wn = warp & 3;
    int bx = blockIdx.x;
    int m0 = (bx >> 2) * 128;     // 0..8064
    int n0 = (bx & 3) * 64;
    bool isImag = (m0 >= 4096);
    int mrow0 = m0 & 4095;

    float acc[4][2][4];
    #pragma unroll
    for (int mt = 0; mt < 4; mt++)
        #pragma unroll
        for (int nt = 0; nt < 2; nt++)
            #pragma unroll
            for (int r = 0; r < 4; r++) acc[mt][nt][r] = 0.f;

    unsigned a_hi_base = (unsigned)__cvta_generic_to_shared(ash);
    unsigned a_lo_base = (unsigned)__cvta_generic_to_shared(asl);
    unsigned w_hi_base = (unsigned)__cvta_generic_to_shared(wsh);
    unsigned w_lo_base = (unsigned)__cvta_generic_to_shared(wsl);
    unsigned a_off = ((wm * 64 + (lane & 15)) * (AST * 2) + (lane >> 4) * 8) * 2;
    unsigned w_off = (((((lane >> 3) & 1) * 8 + (lane & 7)) * (WST * 2)) + wn * 16 + (lane >> 4) * 8) * 2;

    for (int ks = 0; ks < 16; ks++) {
        int plane = ks >> 3;                 // 0 or 1
        int kc = (ks & 7) * 32;
        const float* Ap = isImag ? (plane ? Z1i : Z0i) : (plane ? Z1r : Z0r);
        gemm_chunk(ash, asl, wsh, wsl, a_hi_base, a_lo_base, w_hi_base, w_lo_base,
                   a_off, w_off, Ap, W + plane * 65536, mrow0, n0, kc, tid, acc);
    }

    // raw partial epilogue -> Cp (full 0..8191 row index, no sign/bias)
    int g = lane >> 2, tig = lane & 3;
    #pragma unroll
    for (int mt = 0; mt < 4; mt++) {
        #pragma unroll
        for (int nt = 0; nt < 2; nt++) {
            int n = n0 + wn * 16 + nt * 8 + tig * 2;
            int ml0 = m0 + wm * 64 + mt * 16 + g;
            float* c0 = acc[mt][nt];
            *reinterpret_cast<float2*>(&Cp[ml0 * 256 + n])       = make_float2(c0[0], c0[1]);
            *reinterpret_cast<float2*>(&Cp[(ml0 + 8) * 256 + n]) = make_float2(c0[2], c0[3]);
        }
    }
}

// ---------------- gemm_B: plane 2 (+ partial C), sign + bias epilogue ----------------
__global__ void __launch_bounds__(256, 2)
gemm_b_kernel(const float* __restrict__ A2r, const float* __restrict__ A2i,
              const float* __restrict__ W, const float* __restrict__ Cp,
              const float* __restrict__ bias,
              float* __restrict__ Hr, float* __restrict__ Hi) {
    __shared__ unsigned ash[128 * AST], asl[128 * AST];
    __shared__ unsigned wsh[32 * WST],  wsl[32 * WST];

    int tid = threadIdx.x;
    int lane = tid & 31;
    int warp = tid >> 5;
    int wm = warp >> 2;
    int wn = warp & 3;
    int m0 = blockIdx.y * 128;
    int n0 = blockIdx.x * 64;
    bool isImag = (m0 >= 4096);
    int mrow0 = m0 & 4095;

    int g = lane >> 2, tig = lane & 3;
    float acc[4][2][4];
    #pragma unroll
    for (int mt = 0; mt < 4; mt++) {
        #pragma unroll
        for (int nt = 0; nt < 2; nt++) {
            int n = n0 + wn * 16 + nt * 8 + tig * 2;
            int ml0 = m0 + wm * 64 + mt * 16 + g;
            float2 p0 = *reinterpret_cast<const float2*>(&Cp[ml0 * 256 + n]);
            float2 p1 = *reinterpret_cast<const float2*>(&Cp[(ml0 + 8) * 256 + n]);
            acc[mt][nt][0] = p0.x; acc[mt][nt][1] = p0.y;
            acc[mt][nt][2] = p1.x; acc[mt][nt][3] = p1.y;
        }
    }

    unsigned a_hi_base = (unsigned)__cvta_generic_to_shared(ash);
    unsigned a_lo_base = (unsigned)__cvta_generic_to_shared(asl);
    unsigned w_hi_base = (unsigned)__cvta_generic_to_shared(wsh);
    unsigned w_lo_base = (unsigned)__cvta_generic_to_shared(wsl);
    unsigned a_off = ((wm * 64 + (lane & 15)) * (AST * 2) + (lane >> 4) * 8) * 2;
    unsigned w_off = (((((lane >> 3) & 1) * 8 + (lane & 7)) * (WST * 2)) + wn * 16 + (lane >> 4) * 8) * 2;

    const float* Ap = isImag ? A2i : A2r;
    for (int ks = 0; ks < 8; ks++) {
        gemm_chunk(ash, asl, wsh, wsl, a_hi_base, a_lo_base, w_hi_base, w_lo_base,
                   a_off, w_off, Ap, W + 2 * 65536, mrow0, n0, ks * 32, tid, acc);
    }

    // final epilogue (R2): rows<4096 -> Hi=+C+b ; rows>=4096 -> Hr=-C+b
    #pragma unroll
    for (int mt = 0; mt < 4; mt++) {
        #pragma unroll
        for (int nt = 0; nt < 2; nt++) {
            int n = n0 + wn * 16 + nt * 8 + tig * 2;
            float b0 = bias[n], b1v = bias[n + 1];
            int ml0 = mrow0 + wm * 64 + mt * 16 + g;
            float* c0 = acc[mt][nt];
            if (!isImag) {
                *reinterpret_cast<float2*>(&Hi[ml0 * 256 + n]) =
                    make_float2(c0[0] + b0, c0[1] + b1v);
                *reinterpret_cast<float2*>(&Hi[(ml0 + 8) * 256 + n]) =
                    make_float2(c0[2] + b0, c0[3] + b1v);
            } else {
                *reinterpret_cast<float2*>(&Hr[ml0 * 256 + n]) =
                    make_float2(-c0[0] + b0, -c0[1] + b1v);
                *reinterpret_cast<float2*>(&Hr[(ml0 + 8) * 256 + n]) =
                    make_float2(-c0[2] + b0, -c0[3] + b1v);
            }
        }
    }
}

// ---------------- classifier + log_softmax (R2-proven) ----------------
__global__ void classifier_kernel(const float* __restrict__ Hr, const float* __restrict__ Hi,
                                  const float* __restrict__ Wc, const float* __restrict__ bc,
                                  float* __restrict__ out) {
    int row = blockIdx.x;
    int t = threadIdx.x;   // 128
    __shared__ float x[512];
    __shared__ float lg[40];
    for (int i = t; i < 256; i += 128) {
        x[i]       = Hr[row * 256 + i];
        x[i + 256] = Hi[row * 256 + i];
    }
    __syncthreads();
    int warp = t >> 5, lane = t & 31;
    for (int c = warp; c < 40; c += 4) {
        float s = 0.f;
        #pragma unroll
        for (int k = lane; k < 512; k += 32) s = fmaf(x[k], Wc[c * 512 + k], s);
        #pragma unroll
        for (int o = 16; o > 0; o >>= 1) s += __shfl_xor_sync(0xffffffffu, s, o);
        if (lane == 0) lg[c] = s + bc[c];
    }
    __syncthreads();
    if (warp == 0) {
        float a  = (lane < 40)      ? lg[lane]      : -3.4e38f;
        float b2 = (lane + 32 < 40) ? lg[lane + 32] : -3.4e38f;
        float m = fmaxf(a, b2);
        #pragma unroll
        for (int o = 16; o > 0; o >>= 1) m = fmaxf(m, __shfl_xor_sync(0xffffffffu, m, o));
        float s = ((lane < 40) ? expf(a - m) : 0.f) + ((lane + 32 < 40) ? expf(b2 - m) : 0.f);
        #pragma unroll
        for (int o = 16; o > 0; o >>= 1) s += __shfl_xor_sync(0xffffffffu, s, o);
        float lse = m + logf(s);
        if (lane < 40)      out[row * 40 + lane]      = a - lse;
        if (lane + 32 < 40) out[row * 40 + lane + 32] = b2 - lse;
    }
}

// ---------------- launch ----------------
extern "C" void kernel_launch(void* const* d_in, const int* in_sizes, int n_in,
                              void* d_out, int out_size) {
    const float* real = (const float*)d_in[0];
    const float* imag = (const float*)d_in[1];
    const int*   edges = (const int*)d_in[2];
    const float* qp = (const float*)d_in[3];
    const float* ew = (const float*)d_in[4];
    const float* W1 = (const float*)d_in[5];
    const float* b1 = (const float*)d_in[6];
    const float* W2 = (const float*)d_in[7];
    const float* b2 = (const float*)d_in[8];
    const float* Wc = (const float*)d_in[9];
    const float* bc = (const float*)d_in[10];
    float* out = (float*)d_out;
    int E = in_sizes[4];

    float *Z1r, *Z1i, *Z2r, *Z2i, *H1r, *H1i, *H2r, *H2i, *Cp;
    cudaGetSymbolAddress((void**)&Z1r, g_Z1r);
    cudaGetSymbolAddress((void**)&Z1i, g_Z1i);
    cudaGetSymbolAddress((void**)&Z2r, g_Z2r);
    cudaGetSymbolAddress((void**)&Z2i, g_Z2i);
    cudaGetSymbolAddress((void**)&H1r, g_H1r);
    cudaGetSymbolAddress((void**)&H1i, g_H1i);
    cudaGetSymbolAddress((void**)&H2r, g_H2r);
    cudaGetSymbolAddress((void**)&H2i, g_H2i);
    cudaGetSymbolAddress((void**)&Cp,  g_Cp);

    // graph build
    zero_kernel<<<TSIZE / 256, 256>>>();
    insert_kernel<<<(E + 255) / 256, 256>>>(edges, ew, E);
    dinv_kernel<<<NN / 256, 256>>>();
    emit_kernel<<<TSIZE / 256, 256>>>(qp);

    // ---- layer 1 ----
    spmm_kernel<<<NN, 256>>>(real, imag, nullptr, nullptr, Z1r, Z1i);          // Z1 = Lc@X
    // overlap: spmm2 (Z2 = 2Lc@Z1 - Z0) with gemm_A (Z0*W0 + Z1*W1 -> Cp)
    combined_kernel<<<NN + 256, 256>>>(Z1r, Z1i, real, imag, Z2r, Z2i, W1, Cp);
    gemm_b_kernel<<<dim3(4, 64), 256>>>(Z2r, Z2i, W1, Cp, b1, H1r, H1i);

    // ---- layer 2 ----
    spmm_kernel<<<NN, 256>>>(H1r, H1i, nullptr, nullptr, Z1r, Z1i);
    combined_kernel<<<NN + 256, 256>>>(Z1r, Z1i, H1r, H1i, Z2r, Z2i, W2, Cp);
    gemm_b_kernel<<<dim3(4, 64), 256>>>(Z2r, Z2i, W2, Cp, b2, H2r, H2i);

    classifier_kernel<<<NN, 128>>>(H2r, H2i, Wc, bc, out);
}